// round 2
// baseline (speedup 1.0000x reference)
#include <cuda_runtime.h>
#include <cuda_bf16.h>
#include <cstdint>

// PointPillarsScatter: out[B, C=64, NY=512, NX=512] <- scatter of feat[P, 64]
// at unique cells given by coords[P, 4] = (b, z, y, x).
//
// Strategy: invert the scatter into a gather, with a SELF-VALIDATING index map
// (no per-call init pass needed):
//   K-scatter: g_idx[b*NY*NX + y*NX + x] = p   (unique cells guaranteed)
//   K-gather : per-CTA tile of 128 consecutive cells:
//       p = g_idx[cell]; valid iff coords[p] maps back to cell.
//       __device__ globals are zero-initialized and only the scatter kernel
//       writes g_idx, so each entry is 0 or a valid point id. Occupied cells
//       are rewritten by K-scatter every call; an entry at an EMPTY cell can
//       never verify (if coords[p] mapped to this cell, the cell would be
//       occupied by p). => deterministic, identical work/output every call.
//       Valid rows are gathered coalesced (2x128B) into smem [64][129]
//       (odd stride => conflict-free transposed access), then written out
//       channel-major: 128 contiguous floats per channel (fully coalesced
//       256MB write that doubles as the zero-fill).

#define NYv 512
#define NXv 512
#define Cv 64
#define CELLS_PER_B (NYv * NXv)
#define MAX_B 4
#define TILE 128

// 4 MB scratch index map (device-global — no allocations allowed).
// Zero-initialized at module load; only k_scatter_idx ever writes it.
__device__ int g_idx[MAX_B * CELLS_PER_B];

__global__ void k_scatter_idx(const int4* __restrict__ coords, int P) {
    int p = blockIdx.x * blockDim.x + threadIdx.x;
    if (p < P) {
        int4 c = coords[p];  // (b, z, y, x)
        int flat = c.x * CELLS_PER_B + c.z * NXv + c.w;
        g_idx[flat] = p;
    }
}

__global__ __launch_bounds__(256) void k_gather(
    const float* __restrict__ feat,
    const int4* __restrict__ coords,
    float* __restrict__ out)
{
    // smem tile: [channel][cell-in-tile], padded to 129 so that the
    // transposed store (consecutive lanes -> consecutive channels, stride 129)
    // is bank-conflict-free (129 mod 32 == 1).
    __shared__ float tile[Cv][TILE + 1];

    const int cell_base = blockIdx.x * TILE;
    const int warp = threadIdx.x >> 5;
    const int lane = threadIdx.x & 31;

    // ---- Phase 1: gather 16 cells per warp ----
    // Lanes 0..15 load + verify this warp's 16 cell indices, then shfl.
    int p_l = -1;
    if (lane < 16) {
        const int cell = cell_base + warp * 16 + lane;
        const int p = g_idx[cell];                 // 0 or a valid point id
        const int4 c = __ldg(&coords[p]);          // L2-hot (just written by K-scatter's read stream)
        const int flat = c.x * CELLS_PER_B + c.z * NXv + c.w;
        if (flat == cell) p_l = p;                 // verified occupied cell
    }

    #pragma unroll
    for (int jj = 0; jj < 16; ++jj) {
        int p = __shfl_sync(0xffffffffu, p_l, jj);
        int j = warp * 16 + jj;
        float v0 = 0.0f, v1 = 0.0f;
        if (p >= 0) {
            const float* row = feat + (size_t)p * Cv;
            v0 = row[lane];        // 128B coalesced
            v1 = row[lane + 32];   // 128B coalesced
        }
        tile[lane][j]      = v0;   // conflict-free (stride 129)
        tile[lane + 32][j] = v1;
    }

    __syncthreads();

    // ---- Phase 2: coalesced channel-major write-out ----
    const int b  = cell_base / CELLS_PER_B;
    const int yx = cell_base % CELLS_PER_B;   // tile never crosses a batch (CELLS_PER_B % TILE == 0)
    float* outb = out + (size_t)b * Cv * CELLS_PER_B + yx;

    #pragma unroll
    for (int k = 0; k < (Cv * TILE) / 256; ++k) {  // 32 iterations
        int flat = k * 256 + threadIdx.x;
        int c = flat >> 7;        // /128
        int j = flat & (TILE - 1);
        outb[(size_t)c * CELLS_PER_B + j] = tile[c][j];
    }
}

extern "C" void kernel_launch(void* const* d_in, const int* in_sizes, int n_in,
                              void* d_out, int out_size) {
    const float* feat   = (const float*)d_in[0];
    const int4*  coords = (const int4*)d_in[1];
    // d_in[2] is batch_size on device; derive B from out_size instead.

    const int P = in_sizes[0] / Cv;
    const int B = out_size / (Cv * CELLS_PER_B);
    const int ncells = B * CELLS_PER_B;

    // K1: scatter point ids into the self-validating map.
    k_scatter_idx<<<(P + 255) / 256, 256>>>(coords, P);

    // K2: verify + gather + transpose + coalesced write (also zero-fills).
    k_gather<<<ncells / TILE, 256>>>(feat, coords, (float*)d_out);
}

// round 3
// speedup vs baseline: 1.0510x; 1.0510x over previous
#include <cuda_runtime.h>
#include <cuda_bf16.h>
#include <cstdint>

// PointPillarsScatter: out[B, C=64, NY=512, NX=512] <- scatter of feat[P, 64]
// at unique cells given by coords[P, 4] = (b, z, y, x).
//
// Inverted to a gather with a SELF-TAGGING 64-bit index map (no init pass,
// no verify load):
//   K-scatter: g_map[cell] = ((cell+1) << 32) | p
//   K-gather : entry valid iff (enc>>32) == cell+1. __device__ globals are
//     zero-initialized and only K-scatter writes g_map, so empty cells keep
//     high-word 0 (never equals cell+1 >= 1) and occupied cells are rewritten
//     identically every call => deterministic output, call-count independent.
//
// k_gather per CTA = 128 consecutive cells:
//   Phase 1: half-warp per cell; lane grabs one float4 of the 256B feature
//            row (LDG.128 fully coalesced, 8 independent loads/warp) and
//            stores STS.128 into an XOR-swizzled 32KB tile (conflict-free).
//   Phase 2: transposed read, lane = (channel c0+(l>>3), cells 4*(l&7)+k):
//            4x LDS.32 (provably conflict-free under the swizzle) + STG.128.
//            The 256MB channel-major write is fully coalesced and doubles as
//            the zero-fill of d_out.
//
// Swizzle: element (c, j) lives at smem word  j*64 + 4*((c>>2) ^ ((j>>2)&7)) + (c&3).

#define NYv 512
#define NXv 512
#define Cv 64
#define CELLS_PER_B (NYv * NXv)
#define MAX_B 4
#define TILE 128

// 8 MB scratch map (device-global; zero-initialized; only k_scatter writes it).
__device__ long long g_map[MAX_B * CELLS_PER_B];

__global__ void k_scatter_idx(const int4* __restrict__ coords, int P) {
    int p = blockIdx.x * blockDim.x + threadIdx.x;
    if (p < P) {
        int4 c = coords[p];  // (b, z, y, x)
        int flat = c.x * CELLS_PER_B + c.z * NXv + c.w;
        g_map[flat] = ((long long)(flat + 1) << 32) | (unsigned int)p;
    }
}

__global__ __launch_bounds__(256) void k_gather(
    const float* __restrict__ feat,
    float* __restrict__ out)
{
    __shared__ float tile[TILE * Cv];   // 32 KB, swizzled, no padding

    const int cell_base = blockIdx.x * TILE;
    const int warp = threadIdx.x >> 5;
    const int lane = threadIdx.x & 31;

    // ---- Phase 1: 16 cells per warp, half-warp per cell ----
    // Lanes 0..15 load+validate this warp's 16 map entries (LDG.64, 128B coalesced).
    int p_l = -1;
    if (lane < 16) {
        const int cell = cell_base + warp * 16 + lane;
        const long long enc = g_map[cell];
        if ((int)(enc >> 32) == cell + 1) p_l = (int)enc;
    }

    const int g = lane & 15;          // float4 group within the 64-float row
    #pragma unroll
    for (int i = 0; i < 8; ++i) {
        const int sub = 2 * i + (lane >> 4);        // which of the 16 cells
        const int j   = warp * 16 + sub;            // cell-in-tile 0..127
        const int p   = __shfl_sync(0xffffffffu, p_l, sub);

        float4 v = make_float4(0.f, 0.f, 0.f, 0.f);
        if (p >= 0)
            v = __ldg((const float4*)feat + (size_t)p * (Cv / 4) + g);

        const int sj = (j >> 2) & 7;                // swizzle key (const per half-warp)
        *(float4*)&tile[j * Cv + 4 * (g ^ sj)] = v; // STS.128, conflict-free
    }

    __syncthreads();

    // ---- Phase 2: conflict-free transposed read + coalesced STG.128 ----
    const int b  = cell_base / CELLS_PER_B;
    const int yx = cell_base % CELLS_PER_B;   // tile never crosses a batch
    float* outb = out + (size_t)b * Cv * CELLS_PER_B + yx;

    const int lhi = lane >> 3;                // 0..3 : channel within group
    const int llo = lane & 7;                 // 0..7 : float4-of-cells
    #pragma unroll
    for (int it = 0; it < 8; ++it) {
        const int id = warp * 8 + it;         // 0..63
        const int g0 = id & 15;               // channel group c0 = 4*g0
        const int jb = id >> 4;               // cell block 0..3 (32 cells)
        const int c  = 4 * g0 + lhi;
        const int jl = jb * 32 + 4 * llo;     // first of 4 cells

        // swizzle key for rows jl..jl+3: (j>>2)&7 = llo (jb*8 ≡ 0 mod 8)
        const int w = jl * Cv + 4 * (g0 ^ llo) + lhi;
        float4 v;
        v.x = tile[w];
        v.y = tile[w + Cv];
        v.z = tile[w + 2 * Cv];
        v.w = tile[w + 3 * Cv];

        *(float4*)(outb + (size_t)c * CELLS_PER_B + jl) = v;  // STG.128
    }
}

extern "C" void kernel_launch(void* const* d_in, const int* in_sizes, int n_in,
                              void* d_out, int out_size) {
    const float* feat   = (const float*)d_in[0];
    const int4*  coords = (const int4*)d_in[1];

    const int P = in_sizes[0] / Cv;
    const int B = out_size / (Cv * CELLS_PER_B);
    const int ncells = B * CELLS_PER_B;

    k_scatter_idx<<<(P + 255) / 256, 256>>>(coords, P);
    k_gather<<<ncells / TILE, 256>>>(feat, (float*)d_out);
}